// round 3
// baseline (speedup 1.0000x reference)
#include <cuda_runtime.h>
#include <cuda_fp16.h>
#include <cstdint>

// ---------------- problem constants ----------------
static constexpr int S_TOK  = 2048;   // tokens (M)
static constexpr int K_DIM  = 4096;   // reduction dim
static constexpr int O_DIM  = 4096;   // outputs (N)
static constexpr int GROUPS = 32;     // K groups of 128

// GEMM tiling (sm80-style multistage mma.sync pipeline — tcgen05 is unavailable
// because the harness targets base sm_103, not sm_103a)
static constexpr int BM = 128;
static constexpr int BN = 128;
static constexpr int BK = 64;          // 64 fp16 = 128 B rows
static constexpr int STAGES = 3;
static constexpr int NT = K_DIM / BK;  // 64 mainloop iterations
static constexpr int STAGE_BYTES = 128 * 128;            // 16 KB per operand per stage
static constexpr uint32_t SMEM_BYTES = 2 * STAGES * STAGE_BYTES;  // 96 KB

// ---------------- scratch (device globals; no allocs allowed) ----------------
__device__ __align__(1024) __half g_Xc[(size_t)S_TOK * K_DIM];   // 16 MB centered activations (fp16, exact ints)
__device__ __align__(1024) __half g_Wd[(size_t)O_DIM * K_DIM];   // 32 MB dequantized weights (fp16)
__device__ float g_xs[S_TOK];                                    // per-token activation scale

// ---------------- PTX helpers (base-arch only) ----------------
__device__ __forceinline__ uint32_t smem_u32(const void* p) {
    uint32_t a;
    asm("{ .reg .u64 t; cvta.to.shared.u64 t, %1; cvt.u32.u64 %0, t; }" : "=r"(a) : "l"(p));
    return a;
}
__device__ __forceinline__ void cp16(uint32_t dst, const void* src) {
    asm volatile("cp.async.cg.shared.global [%0], [%1], 16;" :: "r"(dst), "l"(src) : "memory");
}
__device__ __forceinline__ void ldm_x4(uint32_t* r, uint32_t a) {
    asm volatile("ldmatrix.sync.aligned.m8n8.x4.shared.b16 {%0,%1,%2,%3}, [%4];"
                 : "=r"(r[0]), "=r"(r[1]), "=r"(r[2]), "=r"(r[3]) : "r"(a));
}
__device__ __forceinline__ void mma16816(float* d, const uint32_t* a, const uint32_t* b) {
    asm volatile(
        "mma.sync.aligned.m16n8k16.row.col.f32.f16.f16.f32 "
        "{%0,%1,%2,%3}, {%4,%5,%6,%7}, {%8,%9}, {%0,%1,%2,%3};"
        : "+f"(d[0]), "+f"(d[1]), "+f"(d[2]), "+f"(d[3])
        : "r"(a[0]), "r"(a[1]), "r"(a[2]), "r"(a[3]), "r"(b[0]), "r"(b[1]));
}

// ================= kernel 1: per-token activation quant =================
// centered = clip(rint(x/scale)+zp, 0,255) - zp; integers in [-255,255], exact in fp16
__global__ void __launch_bounds__(256) act_quant_kernel(const float* __restrict__ x)
{
    const int row = blockIdx.x;
    const int t = threadIdx.x;
    const float4* xr = reinterpret_cast<const float4*>(x + (size_t)row * K_DIM);
    float4 v[4];
    float mn = 3.4e38f, mx = -3.4e38f;
#pragma unroll
    for (int i = 0; i < 4; i++) {
        v[i] = xr[t * 4 + i];
        mn = fminf(mn, fminf(fminf(v[i].x, v[i].y), fminf(v[i].z, v[i].w)));
        mx = fmaxf(mx, fmaxf(fmaxf(v[i].x, v[i].y), fmaxf(v[i].z, v[i].w)));
    }
#pragma unroll
    for (int o = 16; o > 0; o >>= 1) {
        mn = fminf(mn, __shfl_xor_sync(0xffffffffu, mn, o));
        mx = fmaxf(mx, __shfl_xor_sync(0xffffffffu, mx, o));
    }
    __shared__ float smn[8], smx[8];
    if ((t & 31) == 0) { smn[t >> 5] = mn; smx[t >> 5] = mx; }
    __syncthreads();
    mn = smn[0]; mx = smx[0];
#pragma unroll
    for (int i = 1; i < 8; i++) { mn = fminf(mn, smn[i]); mx = fmaxf(mx, smx[i]); }

    const float scale = fmaxf((mx - mn) / 255.0f, 1e-5f);
    const float zp = fminf(fmaxf(rintf(-mn / scale), 0.0f), 255.0f);
    const float rs = 1.0f / scale;

    uint4* dst = reinterpret_cast<uint4*>(g_Xc + (size_t)row * K_DIM + t * 16);
#pragma unroll
    for (int h = 0; h < 2; h++) {
        const float4 a = v[2 * h], b = v[2 * h + 1];
        const float in[8] = {a.x, a.y, a.z, a.w, b.x, b.y, b.z, b.w};
        float c[8];
#pragma unroll
        for (int e = 0; e < 8; e++) {
            float q = fminf(fmaxf(rintf(in[e] * rs) + zp, 0.0f), 255.0f);
            c[e] = q - zp;
        }
        __half2 h0 = __floats2half2_rn(c[0], c[1]);
        __half2 h1 = __floats2half2_rn(c[2], c[3]);
        __half2 h2 = __floats2half2_rn(c[4], c[5]);
        __half2 h3 = __floats2half2_rn(c[6], c[7]);
        uint4 u;
        u.x = *reinterpret_cast<uint32_t*>(&h0);
        u.y = *reinterpret_cast<uint32_t*>(&h1);
        u.z = *reinterpret_cast<uint32_t*>(&h2);
        u.w = *reinterpret_cast<uint32_t*>(&h3);
        dst[h] = u;
    }
    if (t == 0) g_xs[row] = scale;
}

// ================= kernel 2: weight dequant (fold group scale into fp16) =================
__global__ void __launch_bounds__(256) w_dequant_kernel(const int* __restrict__ qw,
                                                        const float* __restrict__ wsc,
                                                        const int* __restrict__ wzp)
{
    const int idx = blockIdx.x * 256 + threadIdx.x;   // one thread = 4 K-elements
    const int o = idx >> 10;
    const int k = (idx & 1023) << 2;
    const int g = k >> 7;
    const int4 q = reinterpret_cast<const int4*>(qw)[((size_t)o * K_DIM + k) >> 2];
    const float s = __ldg(wsc + o * GROUPS + g);
    const float z = (float)__ldg(wzp + o * GROUPS + g);
    __half2 h0 = __floats2half2_rn(((float)q.x - z) * s, ((float)q.y - z) * s);
    __half2 h1 = __floats2half2_rn(((float)q.z - z) * s, ((float)q.w - z) * s);
    uint2 u;
    u.x = *reinterpret_cast<uint32_t*>(&h0);
    u.y = *reinterpret_cast<uint32_t*>(&h1);
    *reinterpret_cast<uint2*>(g_Wd + (size_t)o * K_DIM + k) = u;
}

// ================= kernel 3: multistage mma.sync GEMM + fused epilogue =================
// C[m,n] = sum_k Xc[m,k] * Wd[n,k];  out = C * xs[m] + bias[n]
// 256 threads = 8 warps in a 4(m) x 2(n) grid; warp tile 32 x 64.
// B ([N,K] row-major, K-contiguous) is col-major KxN for the mma -> NON-trans
// ldmatrix with n as the 8x8 row axis, exactly like A.
__global__ void __launch_bounds__(256, 2) gemm_kernel(const float* __restrict__ bias,
                                                      float* __restrict__ out)
{
    extern __shared__ __align__(128) char smem[];
    const uint32_t sbA = smem_u32(smem);
    const uint32_t sbB = sbA + STAGES * STAGE_BYTES;

    const int tid = threadIdx.x;
    const int lane = tid & 31;
    const int wid = tid >> 5;
    const int wm = wid & 3;        // 4 warps along M (32 rows each)
    const int wn = wid >> 2;       // 2 warps along N (64 cols each)
    const int m0 = blockIdx.y * BM;
    const int n0 = blockIdx.x * BN;

    // ldmatrix lane addressing: lanes 0-15 -> rows 0-15 (k-chunk lcb=0),
    // lanes 16-31 -> same rows, k-chunk lcb=1 (k+8 halves -> matrices 2,3)
    const int lrow = lane & 15;
    const int lcb  = lane >> 4;

    float c[2][8][4];
#pragma unroll
    for (int mi = 0; mi < 2; mi++)
#pragma unroll
        for (int nf = 0; nf < 8; nf++)
#pragma unroll
            for (int e = 0; e < 4; e++) c[mi][nf][e] = 0.0f;

#define LOAD_STAGE(st, kt)                                                          \
    do {                                                                            \
        const __half* gA = g_Xc + (size_t)m0 * K_DIM + (kt) * BK;                   \
        const __half* gB = g_Wd + (size_t)n0 * K_DIM + (kt) * BK;                   \
        _Pragma("unroll")                                                           \
        for (int i = 0; i < 4; i++) {                                               \
            const int cid = tid + i * 256;                                          \
            const int row = cid >> 3;                                               \
            const int ch  = cid & 7;                                                \
            const uint32_t off = (uint32_t)(row * 128 + ((ch ^ (row & 7)) << 4));   \
            cp16(sbA + (st) * STAGE_BYTES + off, gA + (size_t)row * K_DIM + ch * 8);\
            cp16(sbB + (st) * STAGE_BYTES + off, gB + (size_t)row * K_DIM + ch * 8);\
        }                                                                           \
    } while (0)

    // prologue: fill stages 0..STAGES-2
    LOAD_STAGE(0, 0);
    asm volatile("cp.async.commit_group;" ::: "memory");
    LOAD_STAGE(1, 1);
    asm volatile("cp.async.commit_group;" ::: "memory");

    int st = 0;        // compute stage
    int stw = 2;       // write stage
    for (int kt = 0; kt < NT; kt++) {
        asm volatile("cp.async.wait_group 1;" ::: "memory");
        __syncthreads();

        const int nk = kt + STAGES - 1;
        if (nk < NT) { LOAD_STAGE(stw, nk); }
        asm volatile("cp.async.commit_group;" ::: "memory");
        stw = (stw == STAGES - 1) ? 0 : stw + 1;

        const uint32_t baseA = sbA + st * STAGE_BYTES;
        const uint32_t baseB = sbB + st * STAGE_BYTES;
#pragma unroll
        for (int ks = 0; ks < 4; ks++) {
            uint32_t a[2][4];
            uint32_t b[8][2];
#pragma unroll
            for (int mi = 0; mi < 2; mi++) {
                const int row = wm * 32 + mi * 16 + lrow;
                const uint32_t ad =
                    baseA + row * 128 + (((ks * 2 + lcb) ^ (row & 7)) << 4);
                ldm_x4(a[mi], ad);
            }
#pragma unroll
            for (int nj = 0; nj < 4; nj++) {
                const int row = wn * 64 + nj * 16 + lrow;
                const uint32_t bd =
                    baseB + row * 128 + (((ks * 2 + lcb) ^ (row & 7)) << 4);
                uint32_t r[4];
                ldm_x4(r, bd);                 // non-trans: rows are n, cols are k
                b[nj * 2 + 0][0] = r[0];       // n 0-7,  k 0-7
                b[nj * 2 + 1][0] = r[1];       // n 8-15, k 0-7
                b[nj * 2 + 0][1] = r[2];       // n 0-7,  k 8-15
                b[nj * 2 + 1][1] = r[3];       // n 8-15, k 8-15
            }
#pragma unroll
            for (int mi = 0; mi < 2; mi++)
#pragma unroll
                for (int nf = 0; nf < 8; nf++)
                    mma16816(c[mi][nf], a[mi], b[nf]);
        }
        st = (st == STAGES - 1) ? 0 : st + 1;
    }
#undef LOAD_STAGE

    // -------- fused epilogue: out = acc * xs[m] + bias[n] --------
    const int gm0 = m0 + wm * 32 + (lane >> 2);
    const int gn0 = n0 + wn * 64 + (lane & 3) * 2;
#pragma unroll
    for (int mi = 0; mi < 2; mi++) {
        const int r0 = gm0 + mi * 16;
        const float xs0 = g_xs[r0];
        const float xs1 = g_xs[r0 + 8];
#pragma unroll
        for (int nf = 0; nf < 8; nf++) {
            const int col = gn0 + nf * 8;
            const float b0 = __ldg(bias + col);
            const float b1 = __ldg(bias + col + 1);
            float2 lo, hi;
            lo.x = c[mi][nf][0] * xs0 + b0;
            lo.y = c[mi][nf][1] * xs0 + b1;
            hi.x = c[mi][nf][2] * xs1 + b0;
            hi.y = c[mi][nf][3] * xs1 + b1;
            *reinterpret_cast<float2*>(out + (size_t)r0 * O_DIM + col) = lo;
            *reinterpret_cast<float2*>(out + (size_t)(r0 + 8) * O_DIM + col) = hi;
        }
    }
}

// ================= host launcher =================
extern "C" void kernel_launch(void* const* d_in, const int* in_sizes, int n_in,
                              void* d_out, int out_size)
{
    const float* x    = (const float*)d_in[0];
    const int*   qw   = (const int*)d_in[1];
    const float* wsc  = (const float*)d_in[2];
    const int*   wzp  = (const int*)d_in[3];
    const float* bias = (const float*)d_in[4];
    float* out = (float*)d_out;

    act_quant_kernel<<<S_TOK, 256>>>(x);
    w_dequant_kernel<<<(O_DIM * (K_DIM / 4)) / 256, 256>>>(qw, wsc, wzp);

    cudaFuncSetAttribute(gemm_kernel, cudaFuncAttributeMaxDynamicSharedMemorySize,
                         SMEM_BYTES);
    gemm_kernel<<<dim3(O_DIM / BN, S_TOK / BM), 256, SMEM_BYTES>>>(bias, out);
}